// round 5
// baseline (speedup 1.0000x reference)
#include <cuda_runtime.h>
#include <math.h>

#define Dd   512
#define Hh   1024
#define Bb   4
#define Ss   4096
#define Cc   64
#define NCH  64           // S / CHUNK
#define Mm   256          // B * CHUNK rows per chunk
#define NB   256          // persistent blocks
#define SCALEC (2.0f/131072.0f)   // 2 / (B*C*D)

typedef unsigned long long u64;

// ---------------- persistent device scratch (no allocations allowed) --------
__device__ float g_k[NCH*Mm*Dd];     // chunked [n, B*C, D]
__device__ float g_v[NCH*Mm*Dd];
__device__ float g_q[NCH*Mm*Dd];
__device__ float g_y[NCH*Mm*Dd];
__device__ float g_W1e[Hh*Dd];       // Wm1 + d1
__device__ float g_W2e[Dd*Hh];       // Wm2 + d2
__device__ float g_d1[Hh*Dd];
__device__ float g_d2[Dd*Hh];
__device__ float g_m1[Hh*Dd];
__device__ float g_m2[Dd*Hh];
__device__ float g_pre1[Mm*Hh];
__device__ float g_a1[Mm*Hh];
__device__ float g_db2[Mm*Dd];
__device__ float g_db1[Mm*Hh];
__device__ float g_hbuf[Mm*Hh];
__device__ float g_gates[3*NCH];     // decay[64], lr[64], eta[64]
__device__ unsigned g_bar_count;
__device__ unsigned g_bar_sense;

__device__ __forceinline__ float sigmoidf_(float x){ return 1.0f/(1.0f + expf(-x)); }
__device__ __forceinline__ float siluf_(float x){ return x * sigmoidf_(x); }
__device__ __forceinline__ float dsiluf_(float x){ float s = sigmoidf_(x); return s*(1.0f + x*(1.0f - s)); }
__device__ __forceinline__ float clip1f_(float x){ return fminf(1.0f, fmaxf(-1.0f, x)); }

// ---------------- packed f32x2 helpers (Blackwell FFMA2 path) ----------------
__device__ __forceinline__ u64 ffma2_(u64 a, u64 b, u64 c){
    u64 d; asm("fma.rn.f32x2 %0, %1, %2, %3;" : "=l"(d) : "l"(a), "l"(b), "l"(c)); return d;
}
__device__ __forceinline__ u64 pack2_(float x){
    u64 d; asm("mov.b64 %0, {%1, %1};" : "=l"(d) : "f"(x)); return d;
}
__device__ __forceinline__ float2 unpack2_(u64 v){
    float2 f; asm("mov.b64 {%0, %1}, %2;" : "=f"(f.x), "=f"(f.y) : "l"(v)); return f;
}

// ---------------- grid-wide sense-reversal barrier ---------------------------
__device__ __forceinline__ void gsync(unsigned &sense)
{
    __syncthreads();
    if (threadIdx.x == 0 && threadIdx.y == 0) {
        sense ^= 1u;
        __threadfence();                                   // release my writes
        if (atomicAdd(&g_bar_count, 1u) == (unsigned)(NB - 1)) {
            atomicExch(&g_bar_count, 0u);
            __threadfence();
            atomicExch(&g_bar_sense, sense);
        } else {
            while (atomicAdd(&g_bar_sense, 0u) != sense) { __nanosleep(64); }
        }
        __threadfence();                                   // acquire
    }
    __syncthreads();
}

// ---------------- generic TMxTNx16 SGEMM tile core ---------------------------
// LAYOUT 0 (NT): C[m,n] = sum_k A[m,k] * B[n,k]
// LAYOUT 1 (NN): C[m,n] = sum_k A[m,k] * B[k,n]
// LAYOUT 2 (TN): C[m,n] = sum_k A[k,m] * B[k,n]
// blockDim = (TN/4, TM/4); each thread computes a 4x4 micro-tile held as
// 4x2 packed f32x2 accumulators.
template<int LAYOUT, int TM, int TN>
__device__ __forceinline__ void gemm_block(
    const float* __restrict__ A, const float* __restrict__ B,
    int K, int lda, int ldb, int m0, int n0, u64 acc[4][2])
{
    constexpr int THREADS = (TM/4)*(TN/4);
    __shared__ __align__(16) float As[16][TM+4];
    __shared__ __align__(16) float Bs[16][TN+4];
    const int tx = threadIdx.x, ty = threadIdx.y;
    const int tid = ty * (TN/4) + tx;

    for (int k0 = 0; k0 < K; k0 += 16) {
        if (LAYOUT == 0 || LAYOUT == 1) {           // A[m,k] row-major
            #pragma unroll
            for (int i = tid; i < TM*4; i += THREADS) {
                int row = i >> 2, kq = (i & 3) * 4;
                float4 av = *(const float4*)&A[(size_t)(m0 + row) * lda + k0 + kq];
                As[kq+0][row]=av.x; As[kq+1][row]=av.y;
                As[kq+2][row]=av.z; As[kq+3][row]=av.w;
            }
        } else {                                    // A[k,m] row-major
            #pragma unroll
            for (int i = tid; i < TM*4; i += THREADS) {
                int kr = i / (TM/4), mq = (i % (TM/4)) * 4;
                *(float4*)&As[kr][mq] = *(const float4*)&A[(size_t)(k0+kr)*lda + m0 + mq];
            }
        }
        if (LAYOUT == 0) {                          // B[n,k] row-major
            #pragma unroll
            for (int i = tid; i < TN*4; i += THREADS) {
                int row = i >> 2, kq = (i & 3) * 4;
                float4 bv = *(const float4*)&B[(size_t)(n0 + row) * ldb + k0 + kq];
                Bs[kq+0][row]=bv.x; Bs[kq+1][row]=bv.y;
                Bs[kq+2][row]=bv.z; Bs[kq+3][row]=bv.w;
            }
        } else {                                    // B[k,n] row-major
            #pragma unroll
            for (int i = tid; i < TN*4; i += THREADS) {
                int kr = i / (TN/4), nq = (i % (TN/4)) * 4;
                *(float4*)&Bs[kr][nq] = *(const float4*)&B[(size_t)(k0+kr)*ldb + n0 + nq];
            }
        }
        __syncthreads();
        #pragma unroll
        for (int kk = 0; kk < 16; kk++) {
            float4 a4 = *(const float4*)&As[kk][ty*4];
            ulonglong2 b2 = *(const ulonglong2*)&Bs[kk][tx*4];
            u64 ap0 = pack2_(a4.x), ap1 = pack2_(a4.y);
            u64 ap2 = pack2_(a4.z), ap3 = pack2_(a4.w);
            acc[0][0] = ffma2_(ap0, b2.x, acc[0][0]);
            acc[0][1] = ffma2_(ap0, b2.y, acc[0][1]);
            acc[1][0] = ffma2_(ap1, b2.x, acc[1][0]);
            acc[1][1] = ffma2_(ap1, b2.y, acc[1][1]);
            acc[2][0] = ffma2_(ap2, b2.x, acc[2][0]);
            acc[2][1] = ffma2_(ap2, b2.y, acc[2][1]);
            acc[3][0] = ffma2_(ap3, b2.x, acc[3][0]);
            acc[3][1] = ffma2_(ap3, b2.y, acc[3][1]);
        }
        __syncthreads();
    }
}

// ---------------- init: reset fast-weight state every launch -----------------
__global__ void init_kernel(const float* __restrict__ Wm1, const float* __restrict__ Wm2)
{
    int i = blockIdx.x * 256 + threadIdx.x;
    if (i < Hh * Dd) {
        g_d1[i] = 0.0f; g_m1[i] = 0.0f; g_W1e[i] = Wm1[i];
        g_d2[i] = 0.0f; g_m2[i] = 0.0f; g_W2e[i] = Wm2[i];
    }
    if (i == 0) { g_bar_count = 0u; g_bar_sense = 0u; }
}

// ---------------- projections: k/q/v = x @ W^T, written chunked --------------
__global__ __launch_bounds__(256)
void proj_kernel(const float* __restrict__ x,
                 const float* __restrict__ Wk,
                 const float* __restrict__ Wq,
                 const float* __restrict__ Wv)
{
    const float* B = (blockIdx.z == 0) ? Wk : ((blockIdx.z == 1) ? Wq : Wv);
    float* dst     = (blockIdx.z == 0) ? g_k : ((blockIdx.z == 1) ? g_q : g_v);
    u64 acc[4][2] = {};
    int m0 = blockIdx.y * 64, n0 = blockIdx.x * 64;
    gemm_block<0,64,64>(x, B, Dd, Dd, Dd, m0, n0, acc);
    int mbase = m0 + threadIdx.y * 4;
    int nbase = n0 + threadIdx.x * 4;
    #pragma unroll
    for (int i = 0; i < 4; i++) {
        int m = mbase + i;
        int b = m >> 12, s = m & 4095;
        int tt = s >> 6, c = s & 63;
        int row = (tt * Bb + b) * Cc + c;          // chunked row index
        #pragma unroll
        for (int j2 = 0; j2 < 2; j2++) {
            float2 f = unpack2_(acc[i][j2]);
            *(float2*)&dst[(size_t)row * Dd + nbase + j2*2] = f;
        }
    }
}

// ---------------- per-chunk scalar gates -------------------------------------
__global__ void gates_kernel(const float* __restrict__ x,
                             const float* __restrict__ gdw, const float* __restrict__ gdb,
                             const float* __restrict__ glw, const float* __restrict__ glb,
                             const float* __restrict__ gmw, const float* __restrict__ gmb)
{
    int t = blockIdx.x;
    int tid = threadIdx.x;                          // 256 threads, one per (b,c)
    __shared__ float ws[3][Dd];
    for (int j = tid; j < Dd; j += 256) { ws[0][j] = gdw[j]; ws[1][j] = glw[j]; ws[2][j] = gmw[j]; }
    __syncthreads();
    int b = tid >> 6, c = tid & 63;
    const float* xr = x + ((size_t)b * Ss + t * Cc + c) * Dd;
    float s0 = 0.f, s1 = 0.f, s2 = 0.f;
    for (int j = 0; j < Dd; j++) {
        float xv = xr[j];
        s0 += xv * ws[0][j]; s1 += xv * ws[1][j]; s2 += xv * ws[2][j];
    }
    s0 = sigmoidf_(s0 + gdb[0]); s1 = sigmoidf_(s1 + glb[0]); s2 = sigmoidf_(s2 + gmb[0]);
    __shared__ float red[3][256];
    red[0][tid] = s0; red[1][tid] = s1; red[2][tid] = s2;
    __syncthreads();
    for (int o = 128; o > 0; o >>= 1) {
        if (tid < o) {
            red[0][tid] += red[0][tid+o];
            red[1][tid] += red[1][tid+o];
            red[2][tid] += red[2][tid+o];
        }
        __syncthreads();
    }
    if (tid == 0) {
        g_gates[t]          = red[0][0] * (1.0f/256.0f);
        g_gates[NCH + t]    = red[1][0] * (1.0f/256.0f);
        g_gates[2*NCH + t]  = red[2][0] * (1.0f/256.0f);
    }
}

// ---------------- rowwise L2 normalize for k and q ---------------------------
__global__ void norm_kernel()
{
    float* base = blockIdx.y ? g_q : g_k;
    float* row = base + (size_t)blockIdx.x * Dd;
    int tid = threadIdx.x;                          // 128 threads x float4 = 512
    float4 v = reinterpret_cast<float4*>(row)[tid];
    float s = v.x*v.x + v.y*v.y + v.z*v.z + v.w*v.w;
    #pragma unroll
    for (int o = 16; o > 0; o >>= 1) s += __shfl_xor_sync(0xffffffffu, s, o);
    __shared__ float wsum[4];
    if ((tid & 31) == 0) wsum[tid >> 5] = s;
    __syncthreads();
    float tot = wsum[0] + wsum[1] + wsum[2] + wsum[3];
    float inv = 1.0f / (sqrtf(tot) + 1e-8f);
    v.x *= inv; v.y *= inv; v.z *= inv; v.w *= inv;
    reinterpret_cast<float4*>(row)[tid] = v;
}

// ---------------- persistent fused chunk loop --------------------------------
// Stages per chunk t (grid barrier between each):
//  S0: pre1 = kt @ W1e^T       [256,1024]  (128 tiles 32x64, NT)
//  S1: db2  = clip(a1@W2e^T-v) [256, 512]  ( 64 tiles 32x64, NT, K=1024)
//  S2: db1  = (db2@W2e)*silu'  [256,1024]  (128 tiles 32x64, NN)
//  S3: g1=db1^T@kt -> W1e upd; g2=db2^T@a1 -> W2e upd  (256+256 tiles, TN)
//  S4: h = silu(qt @ W1e^T)    [256,1024]  (128 tiles, NT)
//  S5: y = h @ W2e^T           [256, 512]  ( 64 tiles, NT, K=1024)
__global__ __launch_bounds__(128, 2)
void loop_kernel(const float* __restrict__ Wm1, const float* __restrict__ Wm2)
{
    unsigned sense = 0;
    const int bid = blockIdx.x;
    const int tx = threadIdx.x, ty = threadIdx.y;

    for (int t = 0; t < NCH; t++) {
        const float* kt = g_k + (size_t)t*Mm*Dd;
        const float* qt = g_q + (size_t)t*Mm*Dd;
        const float* vt = g_v + (size_t)t*Mm*Dd;
        float* yt = g_y + (size_t)t*Mm*Dd;

        // ---- S0
        for (int tile = bid; tile < 128; tile += NB) {
            int m0 = (tile >> 4) * 32, n0 = (tile & 15) * 64;
            u64 acc[4][2] = {};
            gemm_block<0,32,64>(kt, g_W1e, Dd, Dd, Dd, m0, n0, acc);
            int mb = m0 + ty*4, nb0 = n0 + tx*4;
            #pragma unroll
            for (int i = 0; i < 4; i++)
                #pragma unroll
                for (int j2 = 0; j2 < 2; j2++) {
                    float2 f = unpack2_(acc[i][j2]);
                    int m = mb + i, n = nb0 + j2*2;
                    g_pre1[m*Hh + n]   = f.x;  g_pre1[m*Hh + n+1] = f.y;
                    g_a1[m*Hh + n]     = siluf_(f.x);
                    g_a1[m*Hh + n+1]   = siluf_(f.y);
                }
        }
        gsync(sense);

        // ---- S1
        for (int tile = bid; tile < 64; tile += NB) {
            int m0 = (tile >> 3) * 32, n0 = (tile & 7) * 64;
            u64 acc[4][2] = {};
            gemm_block<0,32,64>(g_a1, g_W2e, Hh, Hh, Hh, m0, n0, acc);
            int mb = m0 + ty*4, nb0 = n0 + tx*4;
            #pragma unroll
            for (int i = 0; i < 4; i++)
                #pragma unroll
                for (int j2 = 0; j2 < 2; j2++) {
                    float2 f = unpack2_(acc[i][j2]);
                    int m = mb + i, n = nb0 + j2*2;
                    float2 o;
                    o.x = clip1f_(f.x - vt[m*Dd + n])   * SCALEC;
                    o.y = clip1f_(f.y - vt[m*Dd + n+1]) * SCALEC;
                    *(float2*)&g_db2[m*Dd + n] = o;
                }
        }
        gsync(sense);

        // ---- S2
        for (int tile = bid; tile < 128; tile += NB) {
            int m0 = (tile >> 4) * 32, n0 = (tile & 15) * 64;
            u64 acc[4][2] = {};
            gemm_block<1,32,64>(g_db2, g_W2e, Dd, Dd, Hh, m0, n0, acc);
            int mb = m0 + ty*4, nb0 = n0 + tx*4;
            #pragma unroll
            for (int i = 0; i < 4; i++)
                #pragma unroll
                for (int j2 = 0; j2 < 2; j2++) {
                    float2 f = unpack2_(acc[i][j2]);
                    int m = mb + i, n = nb0 + j2*2;
                    float2 o;
                    o.x = f.x * dsiluf_(g_pre1[m*Hh + n]);
                    o.y = f.y * dsiluf_(g_pre1[m*Hh + n+1]);
                    *(float2*)&g_db1[m*Hh + n] = o;
                }
        }
        gsync(sense);

        // ---- S3: weight updates
        {
            float dec = g_gates[t], lr = g_gates[NCH + t], eta = g_gates[2*NCH + t];
            for (int tile = bid; tile < 512; tile += NB) {
                u64 acc[4][2] = {};
                if (tile < 256) {                              // g1 [1024,512]
                    int m0 = (tile >> 3) * 32, n0 = (tile & 7) * 64;
                    gemm_block<2,32,64>(g_db1, kt, Mm, Hh, Dd, m0, n0, acc);
                    int mb = m0 + ty*4, nb0 = n0 + tx*4;
                    #pragma unroll
                    for (int i = 0; i < 4; i++)
                        #pragma unroll
                        for (int j2 = 0; j2 < 2; j2++) {
                            float2 f = unpack2_(acc[i][j2]);
                            #pragma unroll
                            for (int u = 0; u < 2; u++) {
                                int idx = (mb + i)*Dd + nb0 + j2*2 + u;
                                float g = clip1f_(u ? f.y : f.x);
                                float mm = eta * g_m1[idx] - lr * g;
                                g_m1[idx] = mm;
                                float dd = (1.0f - dec) * g_d1[idx] + mm;
                                g_d1[idx] = dd;
                                g_W1e[idx] = Wm1[idx] + dd;
                            }
                        }
                } else {                                       // g2 [512,1024]
                    int u2 = tile - 256;
                    int m0 = (u2 >> 4) * 32, n0 = (u2 & 15) * 64;
                    gemm_block<2,32,64>(g_db2, g_a1, Mm, Dd, Hh, m0, n0, acc);
                    int mb = m0 + ty*4, nb0 = n0 + tx*4;
                    #pragma unroll
                    for (int i = 0; i < 4; i++)
                        #pragma unroll
                        for (int j2 = 0; j2 < 2; j2++) {
                            float2 f = unpack2_(acc[i][j2]);
                            #pragma unroll
                            for (int u = 0; u < 2; u++) {
                                int idx = (mb + i)*Hh + nb0 + j2*2 + u;
                                float g = clip1f_(u ? f.y : f.x);
                                float mm = eta * g_m2[idx] - lr * g;
                                g_m2[idx] = mm;
                                float dd = (1.0f - dec) * g_d2[idx] + mm;
                                g_d2[idx] = dd;
                                g_W2e[idx] = Wm2[idx] + dd;
                            }
                        }
                }
            }
        }
        gsync(sense);

        // ---- S4
        for (int tile = bid; tile < 128; tile += NB) {
            int m0 = (tile >> 4) * 32, n0 = (tile & 15) * 64;
            u64 acc[4][2] = {};
            gemm_block<0,32,64>(qt, g_W1e, Dd, Dd, Dd, m0, n0, acc);
            int mb = m0 + ty*4, nb0 = n0 + tx*4;
            #pragma unroll
            for (int i = 0; i < 4; i++)
                #pragma unroll
                for (int j2 = 0; j2 < 2; j2++) {
                    float2 f = unpack2_(acc[i][j2]);
                    int m = mb + i, n = nb0 + j2*2;
                    float2 o; o.x = siluf_(f.x); o.y = siluf_(f.y);
                    *(float2*)&g_hbuf[m*Hh + n] = o;
                }
        }
        gsync(sense);

        // ---- S5
        for (int tile = bid; tile < 64; tile += NB) {
            int m0 = (tile >> 3) * 32, n0 = (tile & 7) * 64;
            u64 acc[4][2] = {};
            gemm_block<0,32,64>(g_hbuf, g_W2e, Hh, Hh, Hh, m0, n0, acc);
            int mb = m0 + ty*4, nb0 = n0 + tx*4;
            #pragma unroll
            for (int i = 0; i < 4; i++)
                #pragma unroll
                for (int j2 = 0; j2 < 2; j2++) {
                    float2 f = unpack2_(acc[i][j2]);
                    int m = mb + i, n = nb0 + j2*2;
                    *(float2*)&yt[m*Dd + n] = f;
                }
        }
        gsync(sense);
    }
}

// ---------------- final: out = y @ Wout^T (undo chunk permutation) -----------
__global__ __launch_bounds__(256)
void final_kernel(const float* __restrict__ Wout, float* __restrict__ out)
{
    u64 acc[4][2] = {};
    int m0 = blockIdx.y * 64, n0 = blockIdx.x * 64;
    gemm_block<0,64,64>(g_y, Wout, Dd, Dd, Dd, m0, n0, acc);
    int mbase = m0 + threadIdx.y * 4;
    int nbase = n0 + threadIdx.x * 4;
    #pragma unroll
    for (int i = 0; i < 4; i++) {
        int m = mbase + i;
        int tt = m >> 8, b = (m >> 6) & 3, c = m & 63;
        size_t orow = (size_t)b * Ss + tt * Cc + c;
        #pragma unroll
        for (int j2 = 0; j2 < 2; j2++) {
            float2 f = unpack2_(acc[i][j2]);
            *(float2*)&out[orow * Dd + nbase + j2*2] = f;
        }
    }
}

// ---------------- launch ------------------------------------------------------
extern "C" void kernel_launch(void* const* d_in, const int* in_sizes, int n_in,
                              void* d_out, int out_size)
{
    const float* x    = (const float*)d_in[0];
    const float* Wk   = (const float*)d_in[1];
    const float* Wv   = (const float*)d_in[2];
    const float* Wq   = (const float*)d_in[3];
    const float* Wout = (const float*)d_in[4];
    const float* Wm1  = (const float*)d_in[5];
    const float* Wm2  = (const float*)d_in[6];
    const float* gd_w = (const float*)d_in[7];
    const float* gd_b = (const float*)d_in[8];
    const float* gl_w = (const float*)d_in[9];
    const float* gl_b = (const float*)d_in[10];
    const float* gm_w = (const float*)d_in[11];
    const float* gm_b = (const float*)d_in[12];
    float* out = (float*)d_out;

    dim3 thr64(16, 16);     // 64x64 tiles
    dim3 thr3264(16, 8);    // 32x64 tiles (loop kernel)

    init_kernel<<<(Hh*Dd + 255)/256, 256>>>(Wm1, Wm2);
    proj_kernel<<<dim3(Dd/64, (Bb*Ss)/64, 3), thr64>>>(x, Wk, Wq, Wv);
    gates_kernel<<<NCH, 256>>>(x, gd_w, gd_b, gl_w, gl_b, gm_w, gm_b);
    norm_kernel<<<dim3(Bb*Ss, 2), 128>>>();

    loop_kernel<<<NB, thr3264>>>(Wm1, Wm2);

    final_kernel<<<dim3(Dd/64, (Bb*Ss)/64), thr64>>>(Wout, out);
}

// round 9
// speedup vs baseline: 1.9186x; 1.9186x over previous
#include <cuda_runtime.h>
#include <math.h>

#define Dd   512
#define Hh   1024
#define Bb   4
#define Ss   4096
#define Cc   64
#define NCH  64           // S / CHUNK
#define Mm   256          // B * CHUNK rows per chunk
#define NB   256          // persistent blocks
#define SCALEC (2.0f/131072.0f)   // 2 / (B*C*D)

typedef unsigned long long u64;

// ---------------- persistent device scratch (no allocations allowed) --------
__device__ float g_k[NCH*Mm*Dd];     // chunked [n, B*C, D]
__device__ float g_v[NCH*Mm*Dd];
__device__ float g_q[NCH*Mm*Dd];
__device__ float g_y[NCH*Mm*Dd];
__device__ float g_W1e[Hh*Dd];       // Wm1 + d1
__device__ float g_W2e[Dd*Hh];       // Wm2 + d2
__device__ float g_d1[Hh*Dd];
__device__ float g_d2[Dd*Hh];
__device__ float g_m1[Hh*Dd];
__device__ float g_m2[Dd*Hh];
__device__ float g_pre1[Mm*Hh];
__device__ float g_a1[Mm*Hh];
__device__ float g_db2[Mm*Dd];
__device__ float g_db1[Mm*Hh];
__device__ float g_hbuf[Mm*Hh];
__device__ float g_gates[3*NCH];     // decay[64], lr[64], eta[64]
__device__ unsigned g_bar_count;
__device__ volatile unsigned g_bar_sense;

__device__ __forceinline__ float sigmoidf_(float x){ return 1.0f/(1.0f + expf(-x)); }
__device__ __forceinline__ float siluf_(float x){ return x * sigmoidf_(x); }
__device__ __forceinline__ float dsiluf_(float x){ float s = sigmoidf_(x); return s*(1.0f + x*(1.0f - s)); }
__device__ __forceinline__ float clip1f_(float x){ return fminf(1.0f, fmaxf(-1.0f, x)); }

// ---------------- packed f32x2 helpers (Blackwell FFMA2 path) ----------------
__device__ __forceinline__ u64 ffma2_(u64 a, u64 b, u64 c){
    u64 d; asm("fma.rn.f32x2 %0, %1, %2, %3;" : "=l"(d) : "l"(a), "l"(b), "l"(c)); return d;
}
__device__ __forceinline__ u64 pack2_(float x){
    u64 d; asm("mov.b64 %0, {%1, %1};" : "=l"(d) : "f"(x)); return d;
}
__device__ __forceinline__ float2 unpack2_(u64 v){
    float2 f; asm("mov.b64 {%0, %1}, %2;" : "=f"(f.x), "=f"(f.y) : "l"(v)); return f;
}

// ---------------- grid-wide sense-reversal barrier (load-poll, no atomic spin)
__device__ __forceinline__ void gsync(unsigned &sense)
{
    __syncthreads();
    if (threadIdx.x == 0 && threadIdx.y == 0) {
        sense ^= 1u;
        __threadfence();                                   // release my writes
        unsigned prev = atomicAdd(&g_bar_count, 1u);
        if (prev == (unsigned)(NB - 1)) {
            g_bar_count = 0u;                              // all arrived; plain reset
            __threadfence();
            g_bar_sense = sense;                           // release
        } else {
            while (g_bar_sense != sense) { }               // volatile LOAD poll (broadcasts)
        }
        __threadfence();                                   // acquire
    }
    __syncthreads();
}

// ---------------- generic TMxTNx16 SGEMM tile core, reg-double-buffered ------
// LAYOUT 0 (NT): C[m,n] = sum_k A[m,k] * B[n,k]
// LAYOUT 1 (NN): C[m,n] = sum_k A[m,k] * B[k,n]
// LAYOUT 2 (TN): C[m,n] = sum_k A[k,m] * B[k,n]
// blockDim = (TN/4, TM/4); each thread computes a 4x4 micro-tile held as
// 4x2 packed f32x2 accumulators. Loads for step k0+16 are issued while
// computing step k0 (register prefetch -> latency hidden under compute).
template<int LAYOUT, int TM, int TN>
__device__ __forceinline__ void gemm_block(
    const float* __restrict__ A, const float* __restrict__ B,
    int K, int lda, int ldb, int m0, int n0, u64 acc[4][2])
{
    constexpr int THREADS = (TM/4)*(TN/4);
    constexpr int NA = (TM*4 + THREADS - 1) / THREADS;   // float4 A-loads per thread
    constexpr int NBl = (TN*4 + THREADS - 1) / THREADS;  // float4 B-loads per thread
    __shared__ __align__(16) float As[16][TM+4];
    __shared__ __align__(16) float Bs[16][TN+4];
    const int tx = threadIdx.x, ty = threadIdx.y;
    const int tid = ty * (TN/4) + tx;

    float4 ra[NA], rb[NBl];

    // ---- prologue: load k0 = 0 into registers
    #pragma unroll
    for (int r = 0; r < NA; r++) {
        int i = tid + r*THREADS;
        if (LAYOUT == 0 || LAYOUT == 1) {
            int row = i >> 2, kq = (i & 3) * 4;
            ra[r] = *(const float4*)&A[(size_t)(m0 + row) * lda + kq];
        } else {
            int kr = i / (TM/4), mq = (i % (TM/4)) * 4;
            ra[r] = *(const float4*)&A[(size_t)kr * lda + m0 + mq];
        }
    }
    #pragma unroll
    for (int r = 0; r < NBl; r++) {
        int i = tid + r*THREADS;
        if (LAYOUT == 0) {
            int row = i >> 2, kq = (i & 3) * 4;
            rb[r] = *(const float4*)&B[(size_t)(n0 + row) * ldb + kq];
        } else {
            int kr = i / (TN/4), nq = (i % (TN/4)) * 4;
            rb[r] = *(const float4*)&B[(size_t)kr * ldb + n0 + nq];
        }
    }

    for (int k0 = 0; k0 < K; k0 += 16) {
        __syncthreads();           // previous compute done -> smem free
        // ---- store prefetched regs to smem
        #pragma unroll
        for (int r = 0; r < NA; r++) {
            int i = tid + r*THREADS;
            if (LAYOUT == 0 || LAYOUT == 1) {
                int row = i >> 2, kq = (i & 3) * 4;
                As[kq+0][row]=ra[r].x; As[kq+1][row]=ra[r].y;
                As[kq+2][row]=ra[r].z; As[kq+3][row]=ra[r].w;
            } else {
                int kr = i / (TM/4), mq = (i % (TM/4)) * 4;
                *(float4*)&As[kr][mq] = ra[r];
            }
        }
        #pragma unroll
        for (int r = 0; r < NBl; r++) {
            int i = tid + r*THREADS;
            if (LAYOUT == 0) {
                int row = i >> 2, kq = (i & 3) * 4;
                Bs[kq+0][row]=rb[r].x; Bs[kq+1][row]=rb[r].y;
                Bs[kq+2][row]=rb[r].z; Bs[kq+3][row]=rb[r].w;
            } else {
                int kr = i / (TN/4), nq = (i % (TN/4)) * 4;
                *(float4*)&Bs[kr][nq] = rb[r];
            }
        }
        // ---- issue loads for next k-step (latency hides under compute below)
        int kn = k0 + 16;
        if (kn < K) {
            #pragma unroll
            for (int r = 0; r < NA; r++) {
                int i = tid + r*THREADS;
                if (LAYOUT == 0 || LAYOUT == 1) {
                    int row = i >> 2, kq = (i & 3) * 4;
                    ra[r] = *(const float4*)&A[(size_t)(m0 + row) * lda + kn + kq];
                } else {
                    int kr = i / (TM/4), mq = (i % (TM/4)) * 4;
                    ra[r] = *(const float4*)&A[(size_t)(kn + kr) * lda + m0 + mq];
                }
            }
            #pragma unroll
            for (int r = 0; r < NBl; r++) {
                int i = tid + r*THREADS;
                if (LAYOUT == 0) {
                    int row = i >> 2, kq = (i & 3) * 4;
                    rb[r] = *(const float4*)&B[(size_t)(n0 + row) * ldb + kn + kq];
                } else {
                    int kr = i / (TN/4), nq = (i % (TN/4)) * 4;
                    rb[r] = *(const float4*)&B[(size_t)(kn + kr) * ldb + n0 + nq];
                }
            }
        }
        __syncthreads();           // smem tiles visible
        #pragma unroll
        for (int kk = 0; kk < 16; kk++) {
            float4 a4 = *(const float4*)&As[kk][ty*4];
            ulonglong2 b2 = *(const ulonglong2*)&Bs[kk][tx*4];
            u64 ap0 = pack2_(a4.x), ap1 = pack2_(a4.y);
            u64 ap2 = pack2_(a4.z), ap3 = pack2_(a4.w);
            acc[0][0] = ffma2_(ap0, b2.x, acc[0][0]);
            acc[0][1] = ffma2_(ap0, b2.y, acc[0][1]);
            acc[1][0] = ffma2_(ap1, b2.x, acc[1][0]);
            acc[1][1] = ffma2_(ap1, b2.y, acc[1][1]);
            acc[2][0] = ffma2_(ap2, b2.x, acc[2][0]);
            acc[2][1] = ffma2_(ap2, b2.y, acc[2][1]);
            acc[3][0] = ffma2_(ap3, b2.x, acc[3][0]);
            acc[3][1] = ffma2_(ap3, b2.y, acc[3][1]);
        }
    }
    __syncthreads();
}

// ---------------- init: reset fast-weight state every launch -----------------
__global__ void init_kernel(const float* __restrict__ Wm1, const float* __restrict__ Wm2)
{
    int i = blockIdx.x * 256 + threadIdx.x;
    if (i < Hh * Dd) {
        g_d1[i] = 0.0f; g_m1[i] = 0.0f; g_W1e[i] = Wm1[i];
        g_d2[i] = 0.0f; g_m2[i] = 0.0f; g_W2e[i] = Wm2[i];
    }
    if (i == 0) { g_bar_count = 0u; g_bar_sense = 0u; }
}

// ---------------- projections: k/q/v = x @ W^T, written chunked --------------
__global__ __launch_bounds__(256)
void proj_kernel(const float* __restrict__ x,
                 const float* __restrict__ Wk,
                 const float* __restrict__ Wq,
                 const float* __restrict__ Wv)
{
    const float* B = (blockIdx.z == 0) ? Wk : ((blockIdx.z == 1) ? Wq : Wv);
    float* dst     = (blockIdx.z == 0) ? g_k : ((blockIdx.z == 1) ? g_q : g_v);
    u64 acc[4][2] = {};
    int m0 = blockIdx.y * 64, n0 = blockIdx.x * 64;
    gemm_block<0,64,64>(x, B, Dd, Dd, Dd, m0, n0, acc);
    int mbase = m0 + threadIdx.y * 4;
    int nbase = n0 + threadIdx.x * 4;
    #pragma unroll
    for (int i = 0; i < 4; i++) {
        int m = mbase + i;
        int b = m >> 12, s = m & 4095;
        int tt = s >> 6, c = s & 63;
        int row = (tt * Bb + b) * Cc + c;          // chunked row index
        #pragma unroll
        for (int j2 = 0; j2 < 2; j2++) {
            float2 f = unpack2_(acc[i][j2]);
            *(float2*)&dst[(size_t)row * Dd + nbase + j2*2] = f;
        }
    }
}

// ---------------- per-chunk scalar gates -------------------------------------
__global__ void gates_kernel(const float* __restrict__ x,
                             const float* __restrict__ gdw, const float* __restrict__ gdb,
                             const float* __restrict__ glw, const float* __restrict__ glb,
                             const float* __restrict__ gmw, const float* __restrict__ gmb)
{
    int t = blockIdx.x;
    int tid = threadIdx.x;                          // 256 threads, one per (b,c)
    __shared__ float ws[3][Dd];
    for (int j = tid; j < Dd; j += 256) { ws[0][j] = gdw[j]; ws[1][j] = glw[j]; ws[2][j] = gmw[j]; }
    __syncthreads();
    int b = tid >> 6, c = tid & 63;
    const float* xr = x + ((size_t)b * Ss + t * Cc + c) * Dd;
    float s0 = 0.f, s1 = 0.f, s2 = 0.f;
    for (int j = 0; j < Dd; j++) {
        float xv = xr[j];
        s0 += xv * ws[0][j]; s1 += xv * ws[1][j]; s2 += xv * ws[2][j];
    }
    s0 = sigmoidf_(s0 + gdb[0]); s1 = sigmoidf_(s1 + glb[0]); s2 = sigmoidf_(s2 + gmb[0]);
    __shared__ float red[3][256];
    red[0][tid] = s0; red[1][tid] = s1; red[2][tid] = s2;
    __syncthreads();
    for (int o = 128; o > 0; o >>= 1) {
        if (tid < o) {
            red[0][tid] += red[0][tid+o];
            red[1][tid] += red[1][tid+o];
            red[2][tid] += red[2][tid+o];
        }
        __syncthreads();
    }
    if (tid == 0) {
        g_gates[t]          = red[0][0] * (1.0f/256.0f);
        g_gates[NCH + t]    = red[1][0] * (1.0f/256.0f);
        g_gates[2*NCH + t]  = red[2][0] * (1.0f/256.0f);
    }
}

// ---------------- rowwise L2 normalize for k and q ---------------------------
__global__ void norm_kernel()
{
    float* base = blockIdx.y ? g_q : g_k;
    float* row = base + (size_t)blockIdx.x * Dd;
    int tid = threadIdx.x;                          // 128 threads x float4 = 512
    float4 v = reinterpret_cast<float4*>(row)[tid];
    float s = v.x*v.x + v.y*v.y + v.z*v.z + v.w*v.w;
    #pragma unroll
    for (int o = 16; o > 0; o >>= 1) s += __shfl_xor_sync(0xffffffffu, s, o);
    __shared__ float wsum[4];
    if ((tid & 31) == 0) wsum[tid >> 5] = s;
    __syncthreads();
    float tot = wsum[0] + wsum[1] + wsum[2] + wsum[3];
    float inv = 1.0f / (sqrtf(tot) + 1e-8f);
    v.x *= inv; v.y *= inv; v.z *= inv; v.w *= inv;
    reinterpret_cast<float4*>(row)[tid] = v;
}

// ---------------- persistent fused chunk loop --------------------------------
// Stages per chunk t (grid barrier between each):
//  S0: pre1 = kt @ W1e^T       [256,1024]  (128 tiles 32x64, NT)
//  S1: db2  = clip(a1@W2e^T-v) [256, 512]  ( 64 tiles 32x64, NT, K=1024)
//  S2: db1  = (db2@W2e)*silu'  [256,1024]  (128 tiles 32x64, NN)
//  S3: g1=db1^T@kt -> W1e upd; g2=db2^T@a1 -> W2e upd  (256+256 tiles, TN)
//  S4: h = silu(qt @ W1e^T)    [256,1024]  (128 tiles, NT)
//  S5: y = h @ W2e^T           [256, 512]  ( 64 tiles, NT, K=1024)
__global__ __launch_bounds__(128, 2)
void loop_kernel(const float* __restrict__ Wm1, const float* __restrict__ Wm2)
{
    unsigned sense = 0;
    const int bid = blockIdx.x;
    const int tx = threadIdx.x, ty = threadIdx.y;

    for (int t = 0; t < NCH; t++) {
        const float* kt = g_k + (size_t)t*Mm*Dd;
        const float* qt = g_q + (size_t)t*Mm*Dd;
        const float* vt = g_v + (size_t)t*Mm*Dd;
        float* yt = g_y + (size_t)t*Mm*Dd;

        // ---- S0
        for (int tile = bid; tile < 128; tile += NB) {
            int m0 = (tile >> 4) * 32, n0 = (tile & 15) * 64;
            u64 acc[4][2] = {};
            gemm_block<0,32,64>(kt, g_W1e, Dd, Dd, Dd, m0, n0, acc);
            int mb = m0 + ty*4, nb0 = n0 + tx*4;
            #pragma unroll
            for (int i = 0; i < 4; i++)
                #pragma unroll
                for (int j2 = 0; j2 < 2; j2++) {
                    float2 f = unpack2_(acc[i][j2]);
                    int m = mb + i, n = nb0 + j2*2;
                    g_pre1[m*Hh + n]   = f.x;  g_pre1[m*Hh + n+1] = f.y;
                    g_a1[m*Hh + n]     = siluf_(f.x);
                    g_a1[m*Hh + n+1]   = siluf_(f.y);
                }
        }
        gsync(sense);

        // ---- S1
        for (int tile = bid; tile < 64; tile += NB) {
            int m0 = (tile >> 3) * 32, n0 = (tile & 7) * 64;
            u64 acc[4][2] = {};
            gemm_block<0,32,64>(g_a1, g_W2e, Hh, Hh, Hh, m0, n0, acc);
            int mb = m0 + ty*4, nb0 = n0 + tx*4;
            #pragma unroll
            for (int i = 0; i < 4; i++)
                #pragma unroll
                for (int j2 = 0; j2 < 2; j2++) {
                    float2 f = unpack2_(acc[i][j2]);
                    int m = mb + i, n = nb0 + j2*2;
                    float2 o;
                    o.x = clip1f_(f.x - vt[m*Dd + n])   * SCALEC;
                    o.y = clip1f_(f.y - vt[m*Dd + n+1]) * SCALEC;
                    *(float2*)&g_db2[m*Dd + n] = o;
                }
        }
        gsync(sense);

        // ---- S2
        for (int tile = bid; tile < 128; tile += NB) {
            int m0 = (tile >> 4) * 32, n0 = (tile & 15) * 64;
            u64 acc[4][2] = {};
            gemm_block<1,32,64>(g_db2, g_W2e, Dd, Dd, Hh, m0, n0, acc);
            int mb = m0 + ty*4, nb0 = n0 + tx*4;
            #pragma unroll
            for (int i = 0; i < 4; i++)
                #pragma unroll
                for (int j2 = 0; j2 < 2; j2++) {
                    float2 f = unpack2_(acc[i][j2]);
                    int m = mb + i, n = nb0 + j2*2;
                    float2 o;
                    o.x = f.x * dsiluf_(g_pre1[m*Hh + n]);
                    o.y = f.y * dsiluf_(g_pre1[m*Hh + n+1]);
                    *(float2*)&g_db1[m*Hh + n] = o;
                }
        }
        gsync(sense);

        // ---- S3: weight updates
        {
            float dec = g_gates[t], lr = g_gates[NCH + t], eta = g_gates[2*NCH + t];
            for (int tile = bid; tile < 512; tile += NB) {
                u64 acc[4][2] = {};
                if (tile < 256) {                              // g1 [1024,512]
                    int m0 = (tile >> 3) * 32, n0 = (tile & 7) * 64;
                    gemm_block<2,32,64>(g_db1, kt, Mm, Hh, Dd, m0, n0, acc);
                    int mb = m0 + ty*4, nb0 = n0 + tx*4;
                    #pragma unroll
                    for (int i = 0; i < 4; i++)
                        #pragma unroll
                        for (int j2 = 0; j2 < 2; j2++) {
                            float2 f = unpack2_(acc[i][j2]);
                            #pragma unroll
                            for (int u = 0; u < 2; u++) {
                                int idx = (mb + i)*Dd + nb0 + j2*2 + u;
                                float g = clip1f_(u ? f.y : f.x);
                                float mm = eta * g_m1[idx] - lr * g;
                                g_m1[idx] = mm;
                                float dd = (1.0f - dec) * g_d1[idx] + mm;
                                g_d1[idx] = dd;
                                g_W1e[idx] = Wm1[idx] + dd;
                            }
                        }
                } else {                                       // g2 [512,1024]
                    int u2 = tile - 256;
                    int m0 = (u2 >> 4) * 32, n0 = (u2 & 15) * 64;
                    gemm_block<2,32,64>(g_db2, g_a1, Mm, Dd, Hh, m0, n0, acc);
                    int mb = m0 + ty*4, nb0 = n0 + tx*4;
                    #pragma unroll
                    for (int i = 0; i < 4; i++)
                        #pragma unroll
                        for (int j2 = 0; j2 < 2; j2++) {
                            float2 f = unpack2_(acc[i][j2]);
                            #pragma unroll
                            for (int u = 0; u < 2; u++) {
                                int idx = (mb + i)*Hh + nb0 + j2*2 + u;
                                float g = clip1f_(u ? f.y : f.x);
                                float mm = eta * g_m2[idx] - lr * g;
                                g_m2[idx] = mm;
                                float dd = (1.0f - dec) * g_d2[idx] + mm;
                                g_d2[idx] = dd;
                                g_W2e[idx] = Wm2[idx] + dd;
                            }
                        }
                }
            }
        }
        gsync(sense);

        // ---- S4
        for (int tile = bid; tile < 128; tile += NB) {
            int m0 = (tile >> 4) * 32, n0 = (tile & 15) * 64;
            u64 acc[4][2] = {};
            gemm_block<0,32,64>(qt, g_W1e, Dd, Dd, Dd, m0, n0, acc);
            int mb = m0 + ty*4, nb0 = n0 + tx*4;
            #pragma unroll
            for (int i = 0; i < 4; i++)
                #pragma unroll
                for (int j2 = 0; j2 < 2; j2++) {
                    float2 f = unpack2_(acc[i][j2]);
                    int m = mb + i, n = nb0 + j2*2;
                    float2 o; o.x = siluf_(f.x); o.y = siluf_(f.y);
                    *(float2*)&g_hbuf[m*Hh + n] = o;
                }
        }
        gsync(sense);

        // ---- S5
        for (int tile = bid; tile < 64; tile += NB) {
            int m0 = (tile >> 3) * 32, n0 = (tile & 7) * 64;
            u64 acc[4][2] = {};
            gemm_block<0,32,64>(g_hbuf, g_W2e, Hh, Hh, Hh, m0, n0, acc);
            int mb = m0 + ty*4, nb0 = n0 + tx*4;
            #pragma unroll
            for (int i = 0; i < 4; i++)
                #pragma unroll
                for (int j2 = 0; j2 < 2; j2++) {
                    float2 f = unpack2_(acc[i][j2]);
                    int m = mb + i, n = nb0 + j2*2;
                    *(float2*)&yt[m*Dd + n] = f;
                }
        }
        gsync(sense);
    }
}

// ---------------- final: out = y @ Wout^T (undo chunk permutation) -----------
__global__ __launch_bounds__(256)
void final_kernel(const float* __restrict__ Wout, float* __restrict__ out)
{
    u64 acc[4][2] = {};
    int m0 = blockIdx.y * 64, n0 = blockIdx.x * 64;
    gemm_block<0,64,64>(g_y, Wout, Dd, Dd, Dd, m0, n0, acc);
    int mbase = m0 + threadIdx.y * 4;
    int nbase = n0 + threadIdx.x * 4;
    #pragma unroll
    for (int i = 0; i < 4; i++) {
        int m = mbase + i;
        int tt = m >> 8, b = (m >> 6) & 3, c = m & 63;
        size_t orow = (size_t)b * Ss + tt * Cc + c;
        #pragma unroll
        for (int j2 = 0; j2 < 2; j2++) {
            float2 f = unpack2_(acc[i][j2]);
            *(float2*)&out[orow * Dd + nbase + j2*2] = f;
        }
    }
}

// ---------------- launch ------------------------------------------------------
extern "C" void kernel_launch(void* const* d_in, const int* in_sizes, int n_in,
                              void* d_out, int out_size)
{
    const float* x    = (const float*)d_in[0];
    const float* Wk   = (const float*)d_in[1];
    const float* Wv   = (const float*)d_in[2];
    const float* Wq   = (const float*)d_in[3];
    const float* Wout = (const float*)d_in[4];
    const float* Wm1  = (const float*)d_in[5];
    const float* Wm2  = (const float*)d_in[6];
    const float* gd_w = (const float*)d_in[7];
    const float* gd_b = (const float*)d_in[8];
    const float* gl_w = (const float*)d_in[9];
    const float* gl_b = (const float*)d_in[10];
    const float* gm_w = (const float*)d_in[11];
    const float* gm_b = (const float*)d_in[12];
    float* out = (float*)d_out;

    dim3 thr64(16, 16);     // 64x64 tiles
    dim3 thr3264(16, 8);    // 32x64 tiles (loop kernel)

    init_kernel<<<(Hh*Dd + 255)/256, 256>>>(Wm1, Wm2);
    proj_kernel<<<dim3(Dd/64, (Bb*Ss)/64, 3), thr64>>>(x, Wk, Wq, Wv);
    gates_kernel<<<NCH, 256>>>(x, gd_w, gd_b, gl_w, gl_b, gm_w, gm_b);
    norm_kernel<<<dim3(Bb*Ss, 2), 128>>>();

    loop_kernel<<<NB, thr3264>>>(Wm1, Wm2);

    final_kernel<<<dim3(Dd/64, (Bb*Ss)/64), thr64>>>(Wout, out);
}